// round 10
// baseline (speedup 1.0000x reference)
#include <cuda_runtime.h>

// out = outer(w, x) @ x0 + bias + x  ==  w * dot(x, x0) + bias + x
// D = 8192 floats = 2048 float4.
// R10: 16 CTAs x 512 threads, single launch, one barrier.
// Each CTA redundantly computes the full dot (no inter-CTA dependency).
// Per-thread: 4 float4 of x0 + 4 float4 of x (8 LDG.128) + 3 scalar epilogue
// loads -> 11 front-batched loads, shallow fold, 5-shfl warp reduce,
// 16 warp sums folded via 4x broadcast LDS.128. Scalar epilogue: 1 elem/thread.

#define NCTAS 16
#define NTHR  512
#define NWARP (NTHR / 32)             // 16
#define V4_TOTAL 2048
#define V4_PER_T (V4_TOTAL / NTHR)    // 4 float4 per vector per thread

__global__ void __launch_bounds__(NTHR) cross_fused_kernel(const float4* __restrict__ x0,
                                                           const float4* __restrict__ x,
                                                           const float*  __restrict__ wf,
                                                           const float*  __restrict__ bf,
                                                           const float*  __restrict__ xf,
                                                           float* __restrict__ outf) {
    const int t = threadIdx.x;

    // ---- Front-batch ALL loads (8x LDG.128 + 3x LDG.32) ----
    float4 a[V4_PER_T], xv[V4_PER_T];
    #pragma unroll
    for (int k = 0; k < V4_PER_T; k++) {
        a[k]  = x0[t + k * NTHR];
        xv[k] = x[t + k * NTHR];
    }
    const int ei = blockIdx.x * NTHR + t;   // one scalar output element per thread
    float we = wf[ei];
    float be = bf[ei];
    float xe = xf[ei];

    // Epilogue additive part — independent of the reduction.
    float ce = be + xe;

    // ---- Partial dot: 4 independent chains, shallow fold ----
    float p[V4_PER_T];
    #pragma unroll
    for (int k = 0; k < V4_PER_T; k++) {
        p[k] = (a[k].x * xv[k].x + a[k].y * xv[k].y)
             + (a[k].z * xv[k].z + a[k].w * xv[k].w);
    }
    float s = (p[0] + p[1]) + (p[2] + p[3]);

    // ---- Full warp reduction (5 shfl — proven better than truncation) ----
    #pragma unroll
    for (int o = 16; o > 0; o >>= 1)
        s += __shfl_xor_sync(0xFFFFFFFFu, s, o);

    __shared__ float4 ws4[NWARP / 4];   // 16 warp sums as 4 float4
    float* ws = (float*)ws4;
    const int warp = t >> 5;
    const int lane = t & 31;
    if (lane == 0) ws[warp] = s;
    __syncthreads();

    // Broadcast-load 16 warp sums (4x LDS.128), fold in a 4-deep tree.
    float4 u0 = ws4[0], u1 = ws4[1], u2 = ws4[2], u3 = ws4[3];
    float4 q0, q1;
    q0.x = u0.x + u1.x; q0.y = u0.y + u1.y; q0.z = u0.z + u1.z; q0.w = u0.w + u1.w;
    q1.x = u2.x + u3.x; q1.y = u2.y + u3.y; q1.z = u2.z + u3.z; q1.w = u2.w + u3.w;
    const float sv = ((q0.x + q1.x) + (q0.y + q1.y))
                   + ((q0.z + q1.z) + (q0.w + q1.w));

    // ---- Epilogue: out = w*s + (b + x), one element per thread ----
    outf[ei] = fmaf(we, sv, ce);
}

extern "C" void kernel_launch(void* const* d_in, const int* in_sizes, int n_in,
                              void* d_out, int out_size) {
    const float4* x0 = (const float4*)d_in[0];
    const float4* x  = (const float4*)d_in[1];
    const float*  wf = (const float*)d_in[2];
    const float*  bf = (const float*)d_in[3];
    const float*  xf = (const float*)d_in[1];
    float* outf = (float*)d_out;

    cross_fused_kernel<<<NCTAS, NTHR>>>(x0, x, wf, bf, xf, outf);
}

// round 12
// speedup vs baseline: 1.0385x; 1.0385x over previous
#include <cuda_runtime.h>

// out = outer(w, x) @ x0 + bias + x  ==  w * dot(x, x0) + bias + x
// D = 8192 floats = 2048 float4.
// R11 = R6 (best, 6.56us) + epilogue x-reuse: the dot phase already loads all
// of x into registers (xv[k] = x[t + k*256] spans the vector), and this CTA's
// epilogue element x[blockIdx.x*256 + t] == xv[blockIdx.x]. Select it with an
// unrolled predicated pick (off the critical chain) instead of a third LDG.

#define NCTAS 8
#define NTHR  256
#define NWARP (NTHR / 32)
#define V4_TOTAL 2048
#define V4_PER_T (V4_TOTAL / NTHR)    // 8
#define V4_PER_CTA (V4_TOTAL / NCTAS) // 256

__global__ void __launch_bounds__(NTHR) cross_fused_kernel(const float4* __restrict__ x0,
                                                           const float4* __restrict__ x,
                                                           const float4* __restrict__ w,
                                                           const float4* __restrict__ b,
                                                           float4* __restrict__ out) {
    const int t = threadIdx.x;

    // ---- Front-batch ALL loads (18 independent LDG.128) ----
    float4 a[V4_PER_T], xv[V4_PER_T];
    #pragma unroll
    for (int k = 0; k < V4_PER_T; k++) {
        a[k]  = x0[t + k * NTHR];
        xv[k] = x[t + k * NTHR];
    }
    const int ei = blockIdx.x * V4_PER_CTA + t;
    float4 wv = w[ei];
    float4 bv = b[ei];

    // Epilogue x element: reuse the dot-phase register copy.
    // x[ei] = x[blockIdx.x*256 + t] = xv[blockIdx.x]. Predicated select.
    float4 xe = xv[0];
    #pragma unroll
    for (int k = 1; k < V4_PER_T; k++)
        if (blockIdx.x == (unsigned)k) xe = xv[k];

    // Epilogue additive part — independent of the reduction, fold early.
    float4 cv;
    cv.x = bv.x + xe.x;
    cv.y = bv.y + xe.y;
    cv.z = bv.z + xe.z;
    cv.w = bv.w + xe.w;

    // ---- Partial dot (tree-reassociated, 4 independent chains) ----
    float p[V4_PER_T];
    #pragma unroll
    for (int k = 0; k < V4_PER_T; k++) {
        p[k] = (a[k].x * xv[k].x + a[k].y * xv[k].y)
             + (a[k].z * xv[k].z + a[k].w * xv[k].w);
    }
    float s = ((p[0] + p[1]) + (p[2] + p[3]))
            + ((p[4] + p[5]) + (p[6] + p[7]));

    // ---- Warp reduction (5 shfl — proven fastest variant) ----
    #pragma unroll
    for (int o = 16; o > 0; o >>= 1)
        s += __shfl_xor_sync(0xFFFFFFFFu, s, o);

    __shared__ float4 ws4[NWARP / 4];   // 8 warp sums as 2 float4
    float* ws = (float*)ws4;
    const int warp = t >> 5;
    const int lane = t & 31;
    if (lane == 0) ws[warp] = s;
    __syncthreads();

    // Broadcast-load all 8 warp sums (2x LDS.128), sum locally (3-deep tree).
    float4 u0 = ws4[0];
    float4 u1 = ws4[1];
    const float sv = ((u0.x + u0.y) + (u0.z + u0.w))
                   + ((u1.x + u1.y) + (u1.z + u1.w));

    // ---- Epilogue: out = w*s + (b + x) ----
    float4 o;
    o.x = fmaf(wv.x, sv, cv.x);
    o.y = fmaf(wv.y, sv, cv.y);
    o.z = fmaf(wv.z, sv, cv.z);
    o.w = fmaf(wv.w, sv, cv.w);
    out[ei] = o;
}

extern "C" void kernel_launch(void* const* d_in, const int* in_sizes, int n_in,
                              void* d_out, int out_size) {
    const float4* x0 = (const float4*)d_in[0];
    const float4* x  = (const float4*)d_in[1];
    const float4* w  = (const float4*)d_in[2];
    const float4* b  = (const float4*)d_in[3];
    float4* out = (float4*)d_out;

    cross_fused_kernel<<<NCTAS, NTHR>>>(x0, x, w, b, out);
}